// round 2
// baseline (speedup 1.0000x reference)
#include <cuda_runtime.h>

// Problem dims (fixed by the reference)
#define Bn  4
#define Qn  256
#define KVn 1024
#define Hn  128
#define VSn 256

// Scratch for projected q and k (no cudaMalloc allowed)
__device__ float g_qp[Bn * Qn * Hn];    // [B*Q, H]
__device__ float g_kp[Bn * KVn * Hn];   // [B*KV, H]

// ---------------------------------------------------------------------------
// Kernel 1: project queries->g_qp and keys->g_kp.
// Each block handles 8 rows. 128 threads: thread t owns output column t.
// W column access is coalesced; input rows staged in smem and broadcast.
// ---------------------------------------------------------------------------
__global__ void proj_kernel(const float* __restrict__ queries,
                            const float* __restrict__ keys,
                            const float* __restrict__ Wq,
                            const float* __restrict__ Wk) {
    const int r0 = blockIdx.x * 8;
    const float* in;
    const float* W;
    float* outp;
    if (r0 < Bn * Qn) {
        in   = queries + r0 * Hn;
        W    = Wq;
        outp = g_qp + r0 * Hn;
    } else {
        const int rr = r0 - Bn * Qn;
        in   = keys + rr * Hn;
        W    = Wk;
        outp = g_kp + rr * Hn;
    }
    __shared__ float s[8][Hn];
    const int t = threadIdx.x;
    #pragma unroll
    for (int rr = 0; rr < 8; rr++) s[rr][t] = in[rr * Hn + t];
    __syncthreads();

    float a[8];
    #pragma unroll
    for (int rr = 0; rr < 8; rr++) a[rr] = 0.f;

    #pragma unroll 4
    for (int kk = 0; kk < Hn; kk++) {
        const float w = W[kk * Hn + t];
        #pragma unroll
        for (int rr = 0; rr < 8; rr++)
            a[rr] = fmaf(s[rr][kk], w, a[rr]);
    }
    #pragma unroll
    for (int rr = 0; rr < 8; rr++) outp[rr * Hn + t] = a[rr];
}

// ---------------------------------------------------------------------------
// Accurate fast tanh: tanh(x) = sign(x) * (1 - 2/(1 + e^{2|x|}))
// ex2.approx + rcp.approx are each ~2^-22 rel err -> abs error < ~4e-7.
// Overflow-safe: large |x| -> ex2 = inf -> rcp = 0 -> tanh = sign(x)*1.
// ---------------------------------------------------------------------------
__device__ __forceinline__ float tanh_acc(float x) {
    const float ax = fabsf(x);
    float e;
    asm("ex2.approx.f32 %0, %1;" : "=f"(e) : "f"(ax * 2.885390081777927f)); // 2*log2(e)
    float r;
    asm("rcp.approx.f32 %0, %1;" : "=f"(r) : "f"(e + 1.0f));
    const float t = fmaf(-2.0f, r, 1.0f);
    return copysignf(t, x);
}

// Per-lane partial score for one key (lane owns 4 h-elements).
__device__ __forceinline__ float score4(const float4 q4, const float4 w4,
                                        const float4 k4) {
    float s = w4.x * tanh_acc(q4.x + k4.x);
    s = fmaf(w4.y, tanh_acc(q4.y + k4.y), s);
    s = fmaf(w4.z, tanh_acc(q4.z + k4.z), s);
    s = fmaf(w4.w, tanh_acc(q4.w + k4.w), s);
    return s;
}

// ---------------------------------------------------------------------------
// Kernel 2: one block per (b, i) query row. 256 threads (8 warps).
// Pass 1: warp-per-key scores, 2 keys/iter, loads pipelined 2 deep.
// Pass 2: block softmax, exactly matching the -1e6 masking semantics;
//         valid_len == 0 degenerates to uniform weights over all KV.
// Pass 3: thread-per-output-column weighted sum of values, ILP 8.
// ---------------------------------------------------------------------------
__global__ void attn_kernel(const float* __restrict__ values,
                            const int* __restrict__ valid_lens,
                            const float* __restrict__ wv,
                            float* __restrict__ out) {
    const int blk  = blockIdx.x;
    const int b    = blk & 3;                    // batch-interleaved mapping
    const int row  = (b << 8) | (blk >> 2);      // b*256 + i
    const int tid  = threadIdx.x;
    const int lane = tid & 31;
    const int warp = tid >> 5;

    __shared__ float s_sc[KVn];
    __shared__ float s_rmax[8];
    __shared__ float s_rsum[8];

    const int L     = valid_lens[b];
    const bool uni  = (L <= 0);        // all slots masked -> uniform softmax
    const int effL  = uni ? KVn : L;

    float Z;
    if (!uni) {
        // ---- Pass 1: scores, software-pipelined, 2 keys per iteration ----
        const float4 q4 = *reinterpret_cast<const float4*>(&g_qp[row * Hn + lane * 4]);
        const float4 w4 = *reinterpret_cast<const float4*>(&wv[lane * 4]);
        const float* kbase = g_kp + b * KVn * Hn;

        int j = warp;
        if (j < effL) {
            // prime pipeline (indices clamped into valid range -> safe loads)
            int jB = (j + 8 < effL) ? j + 8 : j;
            float4 ka = *reinterpret_cast<const float4*>(&kbase[j  * Hn + lane * 4]);
            float4 kb = *reinterpret_cast<const float4*>(&kbase[jB * Hn + lane * 4]);

            while (j < effL) {
                const int jn  = j + 16;
                const int jA2 = (jn     < effL) ? jn     : j;
                const int jB2 = (jn + 8 < effL) ? jn + 8 : j;
                const float4 kc = *reinterpret_cast<const float4*>(&kbase[jA2 * Hn + lane * 4]);
                const float4 kd = *reinterpret_cast<const float4*>(&kbase[jB2 * Hn + lane * 4]);

                // two independent MUFU chains
                float s0 = score4(q4, w4, ka);
                float s1 = score4(q4, w4, kb);

                // interleaved butterfly reductions (pipeline the SHFL latency)
                #pragma unroll
                for (int o = 16; o > 0; o >>= 1) {
                    s0 += __shfl_xor_sync(0xffffffffu, s0, o);
                    s1 += __shfl_xor_sync(0xffffffffu, s1, o);
                }
                if (lane == 0) {
                    s_sc[j] = s0;
                    if (j + 8 < effL) s_sc[j + 8] = s1;
                }
                ka = kc;
                kb = kd;
                j  = jn;
            }
        }
        __syncthreads();

        // ---- Pass 2a: block max over [0, effL) ----
        float m = -3.0e38f;
        for (int jj = tid; jj < effL; jj += 256) m = fmaxf(m, s_sc[jj]);
        #pragma unroll
        for (int o = 16; o > 0; o >>= 1)
            m = fmaxf(m, __shfl_xor_sync(0xffffffffu, m, o));
        if (lane == 0) s_rmax[warp] = m;
        __syncthreads();
        float M = s_rmax[0];
        #pragma unroll
        for (int k = 1; k < 8; k++) M = fmaxf(M, s_rmax[k]);

        // ---- Pass 2b: exp + sum ----
        float z = 0.f;
        for (int jj = tid; jj < effL; jj += 256) {
            const float e = __expf(s_sc[jj] - M);
            s_sc[jj] = e;
            z += e;
        }
        #pragma unroll
        for (int o = 16; o > 0; o >>= 1)
            z += __shfl_xor_sync(0xffffffffu, z, o);
        if (lane == 0) s_rsum[warp] = z;
        __syncthreads();
        Z = s_rsum[0];
        #pragma unroll
        for (int k = 1; k < 8; k++) Z += s_rsum[k];
    } else {
        // valid_len == 0: reference gives softmax over all -1e6 -> uniform
        for (int jj = tid; jj < KVn; jj += 256) s_sc[jj] = 1.0f;
        __syncthreads();
        Z = (float)KVn;
    }

    // ---- Pass 3: AV. Thread tid owns output column tid. ILP 8. ----
    const int c = tid;
    const float* vb = values + (size_t)b * KVn * VSn + c;
    float a[8];
    #pragma unroll
    for (int u = 0; u < 8; u++) a[u] = 0.f;

    int j = 0;
    for (; j + 8 <= effL; j += 8) {
        #pragma unroll
        for (int u = 0; u < 8; u++)
            a[u] = fmaf(s_sc[j + u], vb[(j + u) * VSn], a[u]);
    }
    for (; j < effL; j++) a[0] = fmaf(s_sc[j], vb[j * VSn], a[0]);

    const float acc = ((a[0] + a[1]) + (a[2] + a[3])) +
                      ((a[4] + a[5]) + (a[6] + a[7]));
    out[row * VSn + c] = acc / Z;
}

// ---------------------------------------------------------------------------
extern "C" void kernel_launch(void* const* d_in, const int* in_sizes, int n_in,
                              void* d_out, int out_size) {
    const float* queries = (const float*)d_in[0];
    const float* keys    = (const float*)d_in[1];
    const float* values  = (const float*)d_in[2];
    const int*   valid   = (const int*)d_in[3];
    const float* Wq      = (const float*)d_in[4];
    const float* Wk      = (const float*)d_in[5];
    const float* wv      = (const float*)d_in[6];
    float* out           = (float*)d_out;

    proj_kernel<<<(Bn * Qn + Bn * KVn) / 8, 128>>>(queries, keys, Wq, Wk);
    attn_kernel<<<Bn * Qn, 256>>>(values, valid, wv, out);
}